// round 16
// baseline (speedup 1.0000x reference)
#include <cuda_runtime.h>
#include <cuda_bf16.h>
#include <cstdint>

#define NCELLS 50000
#define NGENES 1000
#define NCLS   30
#define NOUT   8
#define EMAXN  800000

#define MB     128          // cells per CTA
#define NB1    48           // B1 rows: 30 Mu*invVar + 8 Wl + 8 Wr + 2 pad
#define NB2    32           // B2 rows: 30 invVar + 2 pad
#define KPAD   1024         // padded gene dim
#define NSUB   32           // 32 subtiles of 32 genes
#define NTILES 16           // B macro tiles of 64 genes
#define PREP_BLKS (((NB1 + NB2) * KPAD) / 256)   // 320

// -------- scratch (device globals; no allocation allowed) --------
__device__ __align__(16) __nv_bfloat16 g_Bx [NB1 * KPAD];  // K-major rows: MuIv|Wl|Wr|0
__device__ __align__(16) __nv_bfloat16 g_Bx2[NB2 * KPAD];  // K-major rows: invVar|0
__device__ float g_Dc[NCLS];
__device__ __align__(16) float g_logP[NCELLS * NCLS];
__device__ __align__(16) float g_xl[NCELLS * NOUT];
__device__ __align__(16) float g_xr[NCELLS * NOUT];
__device__ int   g_src[EMAXN];
__device__ int   g_dst[EMAXN];
__device__ float g_eexp[EMAXN];
__device__ float g_denom[NCELLS];
__device__ int   g_is64;
__device__ double g_ll;
__device__ double g_ce;

// ---------------- helpers ----------------
__device__ __forceinline__ uint32_t smem_u32(const void* p) {
    uint32_t a;
    asm("{ .reg .u64 t; cvta.to.shared.u64 t, %1; cvt.u32.u64 %0, t; }" : "=r"(a) : "l"(p));
    return a;
}
__device__ __forceinline__ uint32_t bf2(float lo, float hi) {
    uint32_t r; asm("cvt.rn.bf16x2.f32 %0, %1, %2;" : "=r"(r) : "f"(hi), "f"(lo)); return r;
}
__device__ __forceinline__ uint32_t sq_bf16x2(uint32_t u) {
    __nv_bfloat162 v = *reinterpret_cast<__nv_bfloat162*>(&u);
    v = __hmul2(v, v);
    return *reinterpret_cast<uint32_t*>(&v);
}
__device__ __forceinline__ void ldm_x2(uint32_t* r, uint32_t addr) {
    asm volatile("ldmatrix.sync.aligned.m8n8.x2.shared.b16 {%0,%1}, [%2];"
        : "=r"(r[0]), "=r"(r[1]) : "r"(addr));
}
__device__ __forceinline__ void mma_bf16(float* d, const uint32_t* a, const uint32_t* b) {
    asm volatile("mma.sync.aligned.m16n8k16.row.col.f32.bf16.bf16.f32 "
        "{%0,%1,%2,%3}, {%4,%5,%6,%7}, {%8,%9}, {%0,%1,%2,%3};"
        : "+f"(d[0]), "+f"(d[1]), "+f"(d[2]), "+f"(d[3])
        : "r"(a[0]), "r"(a[1]), "r"(a[2]), "r"(a[3]), "r"(b[0]), "r"(b[1]));
}
#define CP16(dst, src)   asm volatile("cp.async.cg.shared.global [%0], [%1], 16;" :: "r"(dst), "l"(src))
#define CP_COMMIT()      asm volatile("cp.async.commit_group;")
#define CP_WAIT0()       asm volatile("cp.async.wait_group 0;")
#define CP_WAIT2()       asm volatile("cp.async.wait_group 2;")

// ---------------- init (reset + parallel dtype detect) ----------------
__global__ void k_init(const int* __restrict__ ei) {
    int i = blockIdx.x * blockDim.x + threadIdx.x;
    if (i < 32) {
        int v = ei[2 * i + 1];
        unsigned any = __ballot_sync(0xffffffffu, v != 0);
        if (i == 0) {
            g_is64 = (any == 0);
            g_ll = 0.0; g_ce = 0.0;
        }
    }
    if (i < NCELLS) g_denom[i] = 0.f;
}

// ---------------- prep (B matrices) + dc (D[c]) fused by block range ----------------
__global__ void k_prepdc(const float* __restrict__ Mu, const float* __restrict__ Var,
                         const float* __restrict__ Wl, const float* __restrict__ Wr) {
    const int b = blockIdx.x, t = threadIdx.x;
    if (b < PREP_BLKS) {
        int idx = b * 256 + t;
        int row = idx / KPAD, g = idx % KPAD;
        float v = 0.f;
        if (g < NGENES) {
            if (row < 30)       v = Mu[row * NGENES + g] / Var[row * NGENES + g];
            else if (row < 38)  v = Wl[(row - 30) * NGENES + g];
            else if (row < 46)  v = Wr[(row - 38) * NGENES + g];
            else if (row >= NB1 && row < NB1 + 30) v = 1.0f / Var[(row - NB1) * NGENES + g];
        }
        if (row < NB1) g_Bx [row * KPAD + g]         = __float2bfloat16(v);
        else           g_Bx2[(row - NB1) * KPAD + g] = __float2bfloat16(v);
    } else {
        int c = b - PREP_BLKS;
        float s = 0.f;
        for (int g = t; g < NGENES; g += 256) {
            float mu = Mu[c * NGENES + g];
            s += mu * mu / Var[c * NGENES + g];
        }
        __shared__ float sh[256];
        sh[t] = s; __syncthreads();
        for (int o = 128; o; o >>= 1) { if (t < o) sh[t] += sh[t + o]; __syncthreads(); }
        if (t == 0) g_Dc[c] = sh[0];
    }
}

// ---------------- row softmax: P and logP ----------------
__global__ void k_softmax(const float* __restrict__ W, float* __restrict__ Pout) {
    int warp = (blockIdx.x * blockDim.x + threadIdx.x) >> 5;
    int lane = threadIdx.x & 31;
    int nw   = (gridDim.x * blockDim.x) >> 5;
    for (int i = warp; i < NCELLS; i += nw) {
        float w = (lane < NCLS) ? W[i * NCLS + lane] : -3.4e38f;
        float m = w;
        #pragma unroll
        for (int o = 16; o; o >>= 1) m = fmaxf(m, __shfl_xor_sync(~0u, m, o));
        float e = (lane < NCLS) ? __expf(w - m) : 0.f;
        float s = e;
        #pragma unroll
        for (int o = 16; o; o >>= 1) s += __shfl_xor_sync(~0u, s, o);
        float ls = __logf(s);
        if (lane < NCLS) {
            Pout[i * NCLS + lane]   = e / s;
            g_logP[i * NCLS + lane] = (w - m) - ls;
        }
    }
}

// ---------------- k_main: depth-2 cp.async pipeline, 4xA ring + 3xB ring ----------------
#define ASTRIDE   160
#define OFF_A(b)  ((b) * 20480)                  // 4 bufs: 0..81920
#define OFF_B1(b) (81920 + (b) * 6144)           // 3 bufs: 81920..100352
#define OFF_B2(b) (100352 + (b) * 4096)          // 3 bufs: 100352..112640
#define SM_TOT    112640
#define DSTRIDE   81

__global__ __launch_bounds__(256, 2) void k_main(const float* __restrict__ X,
                                                 const float* __restrict__ S,
                                                 const float* __restrict__ Pout,
                                                 const float* __restrict__ bl,
                                                 const float* __restrict__ br) {
    extern __shared__ __align__(16) uint8_t sm[];

    const int t     = threadIdx.x;
    const int wid   = t >> 5;
    const int lane  = t & 31;
    const int cell0 = blockIdx.x * MB;
    const uint32_t smb = smem_u32(sm);

    const uint32_t a_base = (uint32_t)((16 * wid + (lane >> 2)) * ASTRIDE + (lane & 3) * 8);
    const int b_lr = lane & 7;
    const uint32_t b_rb  = smb + (uint32_t)(b_lr * 128);
    const uint32_t b_xor = (uint32_t)(b_lr << 4);
    const uint32_t b_kh  = (uint32_t)(((lane >> 3) & 1) * 16);

    float acc1[24], acc2[16];
    #pragma unroll
    for (int i = 0; i < 24; i++) acc1[i] = 0.f;
    #pragma unroll
    for (int i = 0; i < 16; i++) acc2[i] = 0.f;

    auto stageA = [&](int sub, int buf) {
        const int g0 = sub * 32;
        #pragma unroll
        for (int j = 0; j < 4; j++) {
            int idx = t + j * 256;
            int row = idx >> 3, i = idx & 7;
            int cell = cell0 + row;
            if (cell < NCELLS && (g0 + i * 4) < NGENES)
                CP16(smb + OFF_A(buf) + row * ASTRIDE + i * 16,
                     (const char*)(X + (size_t)cell * NGENES + g0) + i * 16);
        }
    };
    auto loadB = [&](int mt, int buf) {
        const int g0 = mt * 64;
        for (int idx = t; idx < (NB1 + NB2) * 8; idx += 256) {
            int row = idx >> 3, i = idx & 7;
            uint32_t sw = (uint32_t)((i * 16) ^ ((row & 7) << 4));
            if (row < NB1) {
                CP16(smb + OFF_B1(buf) + row * 128 + sw,
                     (const char*)(g_Bx + row * KPAD + g0) + i * 16);
            } else {
                int rr = row - NB1;
                CP16(smb + OFF_B2(buf) + rr * 128 + sw,
                     (const char*)(g_Bx2 + rr * KPAD + g0) + i * 16);
            }
        }
    };

    // prologue: two groups ahead. G[-2]: A0+B0, G[-1]: A1+B1
    stageA(0, 0); loadB(0, 0); CP_COMMIT();
    stageA(1, 1); loadB(1, 1); CP_COMMIT();

    for (int sub = 0; sub < NSUB; sub++) {
        // issue group G[sub]: A(sub+2) into ring slot (sub+2)%4; B(sub/2+1) at even subs
        if (sub + 2 < NSUB) stageA(sub + 2, (sub + 2) & 3);
        if (!(sub & 1)) {
            int mt = (sub >> 1) + 1;
            if (mt < NTILES && sub >= 2) loadB(mt, mt % 3);   // mt=1 already in prologue
        }
        CP_COMMIT();                     // always: uniform group accounting
        CP_WAIT2();                      // G[sub-2] complete -> A(sub), B(sub/2) ready
        __syncthreads();

        const int abuf = sub & 3;
        const int bbuf = (sub >> 1) % 3;
        #pragma unroll
        for (int ks = 0; ks < 2; ks++) {
            const uint8_t* ap = sm + OFF_A(abuf) + a_base + ks * 64;
            float2 f0 = *(const float2*)(ap);
            float2 f1 = *(const float2*)(ap + 8 * ASTRIDE);
            float2 f2 = *(const float2*)(ap + 32);
            float2 f3 = *(const float2*)(ap + 8 * ASTRIDE + 32);
            uint32_t a[4] = { bf2(f0.x, f0.y), bf2(f1.x, f1.y),
                              bf2(f2.x, f2.y), bf2(f3.x, f3.y) };
            uint32_t a2[4], b[2];
            #pragma unroll
            for (int i = 0; i < 4; i++) a2[i] = sq_bf16x2(a[i]);

            const uint32_t koff = (uint32_t)((sub & 1) * 64 + ks * 32);
            const uint32_t bk = ((koff + b_kh) ^ b_xor) + b_rb;
            #pragma unroll
            for (int nt = 0; nt < 6; nt++) {
                ldm_x2(b, bk + OFF_B1(bbuf) + nt * 1024);
                mma_bf16(acc1 + nt * 4, a, b);
            }
            #pragma unroll
            for (int nt = 0; nt < 4; nt++) {
                ldm_x2(b, bk + OFF_B2(bbuf) + nt * 1024);
                mma_bf16(acc2 + nt * 4, a2, b);
            }
        }
    }
    // drain all cp.async before overlaying D on the A/B rings
    CP_WAIT0();
    __syncthreads();

    float* D = (float*)sm;
    {
        int m_lo = 16 * wid + (lane >> 2);
        int n0   = 2 * (lane & 3);
        #pragma unroll
        for (int nt = 0; nt < 6; nt++) {
            int col = nt * 8 + n0;
            D[m_lo * DSTRIDE + col]           = acc1[nt * 4 + 0];
            D[m_lo * DSTRIDE + col + 1]       = acc1[nt * 4 + 1];
            D[(m_lo + 8) * DSTRIDE + col]     = acc1[nt * 4 + 2];
            D[(m_lo + 8) * DSTRIDE + col + 1] = acc1[nt * 4 + 3];
        }
        #pragma unroll
        for (int nt = 0; nt < 4; nt++) {
            int col = 48 + nt * 8 + n0;
            D[m_lo * DSTRIDE + col]           = acc2[nt * 4 + 0];
            D[m_lo * DSTRIDE + col + 1]       = acc2[nt * 4 + 1];
            D[(m_lo + 8) * DSTRIDE + col]     = acc2[nt * 4 + 2];
            D[(m_lo + 8) * DSTRIDE + col + 1] = acc2[nt * 4 + 3];
        }
    }
    __syncthreads();

    float fdot = 0.f;
    if (t < MB) {
        int cell = cell0 + t;
        if (cell < NCELLS) {
            const float* row = &D[t * DSTRIDE];
            float s1 = S[cell], s2 = s1 * s1;
            #pragma unroll
            for (int c = 0; c < NCLS; c++) {
                float A = row[48 + c];
                float B = row[c];
                float F = -0.5f * (A - 2.f * s1 * B + s2 * g_Dc[c]);
                fdot = fmaf(Pout[cell * NCLS + c], F, fdot);
            }
            float vl[NOUT], vr[NOUT];
            #pragma unroll
            for (int o = 0; o < NOUT; o++) {
                vl[o] = row[30 + o] + __ldg(&bl[o]);
                vr[o] = row[38 + o] + __ldg(&br[o]);
            }
            *(float4*)&g_xl[cell * NOUT]     = make_float4(vl[0], vl[1], vl[2], vl[3]);
            *(float4*)&g_xl[cell * NOUT + 4] = make_float4(vl[4], vl[5], vl[6], vl[7]);
            *(float4*)&g_xr[cell * NOUT]     = make_float4(vr[0], vr[1], vr[2], vr[3]);
            *(float4*)&g_xr[cell * NOUT + 4] = make_float4(vr[4], vr[5], vr[6], vr[7]);
        }
    }
    #pragma unroll
    for (int o = 16; o; o >>= 1) fdot += __shfl_xor_sync(~0u, fdot, o);
    if (wid < 4 && lane == 0) atomicAdd(&g_ll, (double)fdot);
}

// ---------------- edgeA: scalar form (proven) ----------------
__global__ void k_edgeA(const int* __restrict__ ei, const float* __restrict__ att, int E) {
    int e = blockIdx.x * blockDim.x + threadIdx.x;
    if (e >= E) return;
    int s, d;
    if (g_is64) { s = ei[2 * e]; d = ei[2 * (E + e)]; }
    else        { s = ei[e];     d = ei[E + e]; }
    s = ((unsigned)s < NCELLS) ? s : 0;
    d = ((unsigned)d < NCELLS) ? d : 0;
    g_src[e] = s;
    g_dst[e] = d;
    float4 a0 = *(const float4*)&g_xl[s * NOUT];
    float4 a1 = *(const float4*)&g_xl[s * NOUT + 4];
    float4 b0 = *(const float4*)&g_xr[d * NOUT];
    float4 b1 = *(const float4*)&g_xr[d * NOUT + 4];
    float m[8] = { a0.x + b0.x, a0.y + b0.y, a0.z + b0.z, a0.w + b0.w,
                   a1.x + b1.x, a1.y + b1.y, a1.z + b1.z, a1.w + b1.w };
    float ev = 0.f;
    #pragma unroll
    for (int o = 0; o < NOUT; o++) {
        float v = m[o];
        v = (v > 0.f) ? v : 0.2f * v;
        ev = fmaf(v, __ldg(&att[o]), ev);
    }
    float ex = __expf(ev);
    g_eexp[e] = ex;
    atomicAdd(&g_denom[d], ex);
}

// ---------------- edgeB: cross-entropy, warp per 2 edges (ILP x2, proven) ----------------
__global__ void k_edgeB(const float* __restrict__ Pout, int E) {
    int gw   = (blockIdx.x * blockDim.x + threadIdx.x) >> 5;
    int lane = threadIdx.x & 31;
    int nw   = (gridDim.x * blockDim.x) >> 5;
    float acc = 0.f;
    for (int e = gw * 2; e < E; e += nw * 2) {
        int e1ok = (e + 1 < E);
        int s0 = g_src[e], d0 = g_dst[e];
        int s1 = e1ok ? g_src[e + 1] : 0;
        int d1 = e1ok ? g_dst[e + 1] : 0;
        float ex0 = g_eexp[e];
        float ex1 = e1ok ? g_eexp[e + 1] : 0.f;
        float dn0 = g_denom[d0];
        float dn1 = e1ok ? g_denom[d1] : 1.f;
        float p0 = 0.f, l0 = 0.f, p1 = 0.f, l1 = 0.f;
        if (lane < NCLS) {
            p0 = Pout[s0 * NCLS + lane];
            l0 = g_logP[d0 * NCLS + lane];
            if (e1ok) {
                p1 = Pout[s1 * NCLS + lane];
                l1 = g_logP[d1 * NCLS + lane];
            }
        }
        float v0 = p0 * l0, v1 = p1 * l1;
        #pragma unroll
        for (int o = 16; o; o >>= 1) {
            v0 += __shfl_xor_sync(~0u, v0, o);
            v1 += __shfl_xor_sync(~0u, v1, o);
        }
        if (lane == 0) {
            acc = fmaf(ex0 / (dn0 + 1e-16f), v0, acc);
            if (e1ok) acc = fmaf(ex1 / (dn1 + 1e-16f), v1, acc);
        }
    }
    if (lane == 0) atomicAdd(&g_ce, (double)acc);
}

__global__ void k_final(float* out) {
    out[0] = (float)(g_ll / (double)NCELLS);
    out[1] = (float)(-g_ce / (double)NCELLS);
}

extern "C" void kernel_launch(void* const* d_in, const int* in_sizes, int n_in,
                              void* d_out, int out_size) {
    const float* X   = (const float*)d_in[0];
    const float* Mu  = (const float*)d_in[1];
    const float* Var = (const float*)d_in[2];
    const int*   ei  = (const int*)d_in[3];
    const float* W   = (const float*)d_in[4];
    const float* S   = (const float*)d_in[5];
    const float* Wl  = (const float*)d_in[6];
    const float* bl  = (const float*)d_in[7];
    const float* Wr  = (const float*)d_in[8];
    const float* br  = (const float*)d_in[9];
    const float* att = (const float*)d_in[10];
    float* out = (float*)d_out;
    int E = in_sizes[3] / 2;
    if (E > EMAXN) E = EMAXN;

    cudaFuncSetAttribute(k_main, cudaFuncAttributeMaxDynamicSharedMemorySize, SM_TOT);

    k_init   <<<(NCELLS + 255) / 256, 256>>>(ei);                 // 1
    k_prepdc <<<PREP_BLKS + NCLS, 256>>>(Mu, Var, Wl, Wr);        // 2
    k_softmax<<<512, 256>>>(W, out + 2);                          // 3
    k_main   <<<(NCELLS + MB - 1) / MB, 256, SM_TOT>>>(X, S, out + 2, bl, br);  // 4 <- profiled
    k_edgeA  <<<(E + 255) / 256, 256>>>(ei, att, E);              // 5
    k_edgeB  <<<1024, 256>>>(out + 2, E);                         // 6
    k_final  <<<1, 1>>>(out);                                     // 7
}

// round 17
// speedup vs baseline: 1.1557x; 1.1557x over previous
#include <cuda_runtime.h>
#include <cuda_bf16.h>
#include <cstdint>

#define NCELLS 50000
#define NGENES 1000
#define NCLS   30
#define NOUT   8
#define EMAXN  800000

#define MB     128          // cells per CTA
#define NB1    48           // B1 rows: 30 Mu*invVar + 8 Wl + 8 Wr + 2 pad
#define NB2    32           // B2 rows: 30 invVar + 2 pad
#define KPAD   1024         // padded gene dim
#define NSUB   32           // 32 subtiles of 32 genes
#define PREP_BLKS (((NB1 + NB2) * KPAD) / 256)   // 320

// -------- scratch (device globals; no allocation allowed) --------
__device__ __align__(16) __nv_bfloat16 g_Bx [NB1 * KPAD];  // K-major rows: MuIv|Wl|Wr|0
__device__ __align__(16) __nv_bfloat16 g_Bx2[NB2 * KPAD];  // K-major rows: invVar|0
__device__ float g_Dc[NCLS];
__device__ __align__(16) float g_logP[NCELLS * NCLS];
__device__ __align__(16) float g_xl[NCELLS * NOUT];
__device__ __align__(16) float g_xr[NCELLS * NOUT];
__device__ int   g_src[EMAXN];
__device__ int   g_dst[EMAXN];
__device__ float g_eexp[EMAXN];
__device__ float g_denom[NCELLS];
__device__ int   g_is64;
__device__ double g_ll;
__device__ double g_ce;

// ---------------- helpers ----------------
__device__ __forceinline__ uint32_t smem_u32(const void* p) {
    uint32_t a;
    asm("{ .reg .u64 t; cvta.to.shared.u64 t, %1; cvt.u32.u64 %0, t; }" : "=r"(a) : "l"(p));
    return a;
}
__device__ __forceinline__ uint32_t bf2(float lo, float hi) {
    uint32_t r; asm("cvt.rn.bf16x2.f32 %0, %1, %2;" : "=r"(r) : "f"(hi), "f"(lo)); return r;
}
__device__ __forceinline__ uint32_t sq_bf16x2(uint32_t u) {
    __nv_bfloat162 v = *reinterpret_cast<__nv_bfloat162*>(&u);
    v = __hmul2(v, v);
    return *reinterpret_cast<uint32_t*>(&v);
}
__device__ __forceinline__ void ldm_x2(uint32_t* r, uint32_t addr) {
    asm volatile("ldmatrix.sync.aligned.m8n8.x2.shared.b16 {%0,%1}, [%2];"
        : "=r"(r[0]), "=r"(r[1]) : "r"(addr));
}
__device__ __forceinline__ void mma_bf16(float* d, const uint32_t* a, const uint32_t* b) {
    asm volatile("mma.sync.aligned.m16n8k16.row.col.f32.bf16.bf16.f32 "
        "{%0,%1,%2,%3}, {%4,%5,%6,%7}, {%8,%9}, {%0,%1,%2,%3};"
        : "+f"(d[0]), "+f"(d[1]), "+f"(d[2]), "+f"(d[3])
        : "r"(a[0]), "r"(a[1]), "r"(a[2]), "r"(a[3]), "r"(b[0]), "r"(b[1]));
}
#define CP16(dst, src) asm volatile("cp.async.cg.shared.global [%0], [%1], 16;" :: "r"(dst), "l"(src))
#define CP_COMMIT()    asm volatile("cp.async.commit_group;")
#define CP_WAIT0()     asm volatile("cp.async.wait_group 0;")

// ---------------- init (reset + parallel dtype detect) ----------------
__global__ void k_init(const int* __restrict__ ei) {
    int i = blockIdx.x * blockDim.x + threadIdx.x;
    if (i < 32) {
        int v = ei[2 * i + 1];
        unsigned any = __ballot_sync(0xffffffffu, v != 0);
        if (i == 0) {
            g_is64 = (any == 0);
            g_ll = 0.0; g_ce = 0.0;
        }
    }
    if (i < NCELLS) g_denom[i] = 0.f;
}

// ---------------- prep (B matrices) + dc (D[c]) fused by block range ----------------
__global__ void k_prepdc(const float* __restrict__ Mu, const float* __restrict__ Var,
                         const float* __restrict__ Wl, const float* __restrict__ Wr) {
    const int b = blockIdx.x, t = threadIdx.x;
    if (b < PREP_BLKS) {
        int idx = b * 256 + t;
        int row = idx / KPAD, g = idx % KPAD;
        float v = 0.f;
        if (g < NGENES) {
            if (row < 30)       v = Mu[row * NGENES + g] / Var[row * NGENES + g];
            else if (row < 38)  v = Wl[(row - 30) * NGENES + g];
            else if (row < 46)  v = Wr[(row - 38) * NGENES + g];
            else if (row >= NB1 && row < NB1 + 30) v = 1.0f / Var[(row - NB1) * NGENES + g];
        }
        if (row < NB1) g_Bx [row * KPAD + g]         = __float2bfloat16(v);
        else           g_Bx2[(row - NB1) * KPAD + g] = __float2bfloat16(v);
    } else {
        int c = b - PREP_BLKS;
        float s = 0.f;
        for (int g = t; g < NGENES; g += 256) {
            float mu = Mu[c * NGENES + g];
            s += mu * mu / Var[c * NGENES + g];
        }
        __shared__ float sh[256];
        sh[t] = s; __syncthreads();
        for (int o = 128; o; o >>= 1) { if (t < o) sh[t] += sh[t + o]; __syncthreads(); }
        if (t == 0) g_Dc[c] = sh[0];
    }
}

// ---------------- row softmax: P and logP ----------------
__global__ void k_softmax(const float* __restrict__ W, float* __restrict__ Pout) {
    int warp = (blockIdx.x * blockDim.x + threadIdx.x) >> 5;
    int lane = threadIdx.x & 31;
    int nw   = (gridDim.x * blockDim.x) >> 5;
    for (int i = warp; i < NCELLS; i += nw) {
        float w = (lane < NCLS) ? W[i * NCLS + lane] : -3.4e38f;
        float m = w;
        #pragma unroll
        for (int o = 16; o; o >>= 1) m = fmaxf(m, __shfl_xor_sync(~0u, m, o));
        float e = (lane < NCLS) ? __expf(w - m) : 0.f;
        float s = e;
        #pragma unroll
        for (int o = 16; o; o >>= 1) s += __shfl_xor_sync(~0u, s, o);
        float ls = __logf(s);
        if (lane < NCLS) {
            Pout[i * NCLS + lane]   = e / s;
            g_logP[i * NCLS + lane] = (w - m) - ls;
        }
    }
}

// ---------------- k_main: R15 exact (best measured: 49.6us, 3 CTAs/SM) ----------------
#define ASTRIDE   160
#define OFF_A(b)  ((b) * 20480)
#define OFF_B1(b) (40960 + (b) * 6144)
#define OFF_B2(b) (53248 + (b) * 4096)
#define SM_TOT    61440
#define DSTRIDE   81

__global__ __launch_bounds__(256, 3) void k_main(const float* __restrict__ X,
                                                 const float* __restrict__ S,
                                                 const float* __restrict__ Pout,
                                                 const float* __restrict__ bl,
                                                 const float* __restrict__ br) {
    extern __shared__ __align__(16) uint8_t sm[];

    const int t     = threadIdx.x;
    const int wid   = t >> 5;
    const int lane  = t & 31;
    const int cell0 = blockIdx.x * MB;
    const uint32_t smb = smem_u32(sm);

    const uint32_t a_base = (uint32_t)((16 * wid + (lane >> 2)) * ASTRIDE + (lane & 3) * 8);
    const int b_lr = lane & 7;
    const uint32_t b_rb  = smb + (uint32_t)(b_lr * 128);
    const uint32_t b_xor = (uint32_t)(b_lr << 4);
    const uint32_t b_kh  = (uint32_t)(((lane >> 3) & 1) * 16);

    float acc1[24], acc2[16];
    #pragma unroll
    for (int i = 0; i < 24; i++) acc1[i] = 0.f;
    #pragma unroll
    for (int i = 0; i < 16; i++) acc2[i] = 0.f;

    auto stageA = [&](int sub, int buf) {
        const int g0 = sub * 32;
        #pragma unroll
        for (int j = 0; j < 4; j++) {
            int idx = t + j * 256;
            int row = idx >> 3, i = idx & 7;
            int cell = cell0 + row;
            if (cell < NCELLS && (g0 + i * 4) < NGENES)
                CP16(smb + OFF_A(buf) + row * ASTRIDE + i * 16,
                     (const char*)(X + (size_t)cell * NGENES + g0) + i * 16);
        }
    };
    auto loadB = [&](int mt, int buf) {
        const int g0 = mt * 64;
        for (int idx = t; idx < (NB1 + NB2) * 8; idx += 256) {
            int row = idx >> 3, i = idx & 7;
            uint32_t sw = (uint32_t)((i * 16) ^ ((row & 7) << 4));
            if (row < NB1) {
                CP16(smb + OFF_B1(buf) + row * 128 + sw,
                     (const char*)(g_Bx + row * KPAD + g0) + i * 16);
            } else {
                int rr = row - NB1;
                CP16(smb + OFF_B2(buf) + rr * 128 + sw,
                     (const char*)(g_Bx2 + rr * KPAD + g0) + i * 16);
            }
        }
    };

    stageA(0, 0);
    loadB(0, 0);
    CP_COMMIT();
    CP_WAIT0();
    __syncthreads();

    for (int sub = 0; sub < NSUB; sub++) {
        const int abuf = sub & 1;
        const int bbuf = (sub >> 1) & 1;
        const bool pre = (sub + 1 < NSUB);
        if (pre) {
            stageA(sub + 1, abuf ^ 1);
            if (sub & 1)
                loadB((sub + 1) >> 1, bbuf ^ 1);
            CP_COMMIT();
        }

        #pragma unroll
        for (int ks = 0; ks < 2; ks++) {
            const uint8_t* ap = sm + OFF_A(abuf) + a_base + ks * 64;
            float2 f0 = *(const float2*)(ap);
            float2 f1 = *(const float2*)(ap + 8 * ASTRIDE);
            float2 f2 = *(const float2*)(ap + 32);
            float2 f3 = *(const float2*)(ap + 8 * ASTRIDE + 32);
            uint32_t a[4] = { bf2(f0.x, f0.y), bf2(f1.x, f1.y),
                              bf2(f2.x, f2.y), bf2(f3.x, f3.y) };
            uint32_t a2[4], b[2];
            #pragma unroll
            for (int i = 0; i < 4; i++) a2[i] = sq_bf16x2(a[i]);

            const uint32_t koff = (uint32_t)((sub & 1) * 64 + ks * 32);
            const uint32_t bk = ((koff + b_kh) ^ b_xor) + b_rb;
            #pragma unroll
            for (int nt = 0; nt < 6; nt++) {
                ldm_x2(b, bk + OFF_B1(bbuf) + nt * 1024);
                mma_bf16(acc1 + nt * 4, a, b);
            }
            #pragma unroll
            for (int nt = 0; nt < 4; nt++) {
                ldm_x2(b, bk + OFF_B2(bbuf) + nt * 1024);
                mma_bf16(acc2 + nt * 4, a2, b);
            }
        }

        if (pre) CP_WAIT0();
        __syncthreads();
    }

    float* D = (float*)sm;
    {
        int m_lo = 16 * wid + (lane >> 2);
        int n0   = 2 * (lane & 3);
        #pragma unroll
        for (int nt = 0; nt < 6; nt++) {
            int col = nt * 8 + n0;
            D[m_lo * DSTRIDE + col]           = acc1[nt * 4 + 0];
            D[m_lo * DSTRIDE + col + 1]       = acc1[nt * 4 + 1];
            D[(m_lo + 8) * DSTRIDE + col]     = acc1[nt * 4 + 2];
            D[(m_lo + 8) * DSTRIDE + col + 1] = acc1[nt * 4 + 3];
        }
        #pragma unroll
        for (int nt = 0; nt < 4; nt++) {
            int col = 48 + nt * 8 + n0;
            D[m_lo * DSTRIDE + col]           = acc2[nt * 4 + 0];
            D[m_lo * DSTRIDE + col + 1]       = acc2[nt * 4 + 1];
            D[(m_lo + 8) * DSTRIDE + col]     = acc2[nt * 4 + 2];
            D[(m_lo + 8) * DSTRIDE + col + 1] = acc2[nt * 4 + 3];
        }
    }
    __syncthreads();

    float fdot = 0.f;
    if (t < MB) {
        int cell = cell0 + t;
        if (cell < NCELLS) {
            const float* row = &D[t * DSTRIDE];
            float s1 = S[cell], s2 = s1 * s1;
            #pragma unroll
            for (int c = 0; c < NCLS; c++) {
                float A = row[48 + c];
                float B = row[c];
                float F = -0.5f * (A - 2.f * s1 * B + s2 * g_Dc[c]);
                fdot = fmaf(Pout[cell * NCLS + c], F, fdot);
            }
            float vl[NOUT], vr[NOUT];
            #pragma unroll
            for (int o = 0; o < NOUT; o++) {
                vl[o] = row[30 + o] + __ldg(&bl[o]);
                vr[o] = row[38 + o] + __ldg(&br[o]);
            }
            *(float4*)&g_xl[cell * NOUT]     = make_float4(vl[0], vl[1], vl[2], vl[3]);
            *(float4*)&g_xl[cell * NOUT + 4] = make_float4(vl[4], vl[5], vl[6], vl[7]);
            *(float4*)&g_xr[cell * NOUT]     = make_float4(vr[0], vr[1], vr[2], vr[3]);
            *(float4*)&g_xr[cell * NOUT + 4] = make_float4(vr[4], vr[5], vr[6], vr[7]);
        }
    }
    #pragma unroll
    for (int o = 16; o; o >>= 1) fdot += __shfl_xor_sync(~0u, fdot, o);
    if (wid < 4 && lane == 0) atomicAdd(&g_ll, (double)fdot);
}

// ---------------- edgeA: scalar form (proven) ----------------
__global__ void k_edgeA(const int* __restrict__ ei, const float* __restrict__ att, int E) {
    int e = blockIdx.x * blockDim.x + threadIdx.x;
    if (e >= E) return;
    int s, d;
    if (g_is64) { s = ei[2 * e]; d = ei[2 * (E + e)]; }
    else        { s = ei[e];     d = ei[E + e]; }
    s = ((unsigned)s < NCELLS) ? s : 0;
    d = ((unsigned)d < NCELLS) ? d : 0;
    g_src[e] = s;
    g_dst[e] = d;
    float4 a0 = *(const float4*)&g_xl[s * NOUT];
    float4 a1 = *(const float4*)&g_xl[s * NOUT + 4];
    float4 b0 = *(const float4*)&g_xr[d * NOUT];
    float4 b1 = *(const float4*)&g_xr[d * NOUT + 4];
    float m[8] = { a0.x + b0.x, a0.y + b0.y, a0.z + b0.z, a0.w + b0.w,
                   a1.x + b1.x, a1.y + b1.y, a1.z + b1.z, a1.w + b1.w };
    float ev = 0.f;
    #pragma unroll
    for (int o = 0; o < NOUT; o++) {
        float v = m[o];
        v = (v > 0.f) ? v : 0.2f * v;
        ev = fmaf(v, __ldg(&att[o]), ev);
    }
    float ex = __expf(ev);
    g_eexp[e] = ex;
    atomicAdd(&g_denom[d], ex);
}

// ---------------- edgeB: cross-entropy, warp per 4 edges (ILP x4) ----------------
__global__ void k_edgeB(const float* __restrict__ Pout, int E) {
    int gw   = (blockIdx.x * blockDim.x + threadIdx.x) >> 5;
    int lane = threadIdx.x & 31;
    int nw   = (gridDim.x * blockDim.x) >> 5;
    float acc = 0.f;
    for (int e = gw * 4; e < E; e += nw * 4) {
        int ok1 = (e + 1 < E), ok2 = (e + 2 < E), ok3 = (e + 3 < E);
        int s0 = g_src[e],                 d0 = g_dst[e];
        int s1 = ok1 ? g_src[e + 1] : 0,   d1 = ok1 ? g_dst[e + 1] : 0;
        int s2 = ok2 ? g_src[e + 2] : 0,   d2 = ok2 ? g_dst[e + 2] : 0;
        int s3 = ok3 ? g_src[e + 3] : 0,   d3 = ok3 ? g_dst[e + 3] : 0;
        float ex0 = g_eexp[e];
        float ex1 = ok1 ? g_eexp[e + 1] : 0.f;
        float ex2 = ok2 ? g_eexp[e + 2] : 0.f;
        float ex3 = ok3 ? g_eexp[e + 3] : 0.f;
        float dn0 = g_denom[d0];
        float dn1 = ok1 ? g_denom[d1] : 1.f;
        float dn2 = ok2 ? g_denom[d2] : 1.f;
        float dn3 = ok3 ? g_denom[d3] : 1.f;
        float p0 = 0.f, l0 = 0.f, p1 = 0.f, l1 = 0.f;
        float p2 = 0.f, l2 = 0.f, p3 = 0.f, l3 = 0.f;
        if (lane < NCLS) {
            p0 = Pout[s0 * NCLS + lane];
            l0 = g_logP[d0 * NCLS + lane];
            if (ok1) { p1 = Pout[s1 * NCLS + lane]; l1 = g_logP[d1 * NCLS + lane]; }
            if (ok2) { p2 = Pout[s2 * NCLS + lane]; l2 = g_logP[d2 * NCLS + lane]; }
            if (ok3) { p3 = Pout[s3 * NCLS + lane]; l3 = g_logP[d3 * NCLS + lane]; }
        }
        float v0 = p0 * l0, v1 = p1 * l1, v2 = p2 * l2, v3 = p3 * l3;
        #pragma unroll
        for (int o = 16; o; o >>= 1) {
            v0 += __shfl_xor_sync(~0u, v0, o);
            v1 += __shfl_xor_sync(~0u, v1, o);
            v2 += __shfl_xor_sync(~0u, v2, o);
            v3 += __shfl_xor_sync(~0u, v3, o);
        }
        if (lane == 0) {
            acc = fmaf(ex0 / (dn0 + 1e-16f), v0, acc);
            if (ok1) acc = fmaf(ex1 / (dn1 + 1e-16f), v1, acc);
            if (ok2) acc = fmaf(ex2 / (dn2 + 1e-16f), v2, acc);
            if (ok3) acc = fmaf(ex3 / (dn3 + 1e-16f), v3, acc);
        }
    }
    if (lane == 0) atomicAdd(&g_ce, (double)acc);
}

__global__ void k_final(float* out) {
    out[0] = (float)(g_ll / (double)NCELLS);
    out[1] = (float)(-g_ce / (double)NCELLS);
}

extern "C" void kernel_launch(void* const* d_in, const int* in_sizes, int n_in,
                              void* d_out, int out_size) {
    const float* X   = (const float*)d_in[0];
    const float* Mu  = (const float*)d_in[1];
    const float* Var = (const float*)d_in[2];
    const int*   ei  = (const int*)d_in[3];
    const float* W   = (const float*)d_in[4];
    const float* S   = (const float*)d_in[5];
    const float* Wl  = (const float*)d_in[6];
    const float* bl  = (const float*)d_in[7];
    const float* Wr  = (const float*)d_in[8];
    const float* br  = (const float*)d_in[9];
    const float* att = (const float*)d_in[10];
    float* out = (float*)d_out;
    int E = in_sizes[3] / 2;
    if (E > EMAXN) E = EMAXN;

    cudaFuncSetAttribute(k_main, cudaFuncAttributeMaxDynamicSharedMemorySize, SM_TOT);

    k_init   <<<(NCELLS + 255) / 256, 256>>>(ei);                 // 1
    k_prepdc <<<PREP_BLKS + NCLS, 256>>>(Mu, Var, Wl, Wr);        // 2
    k_softmax<<<512, 256>>>(W, out + 2);                          // 3
    k_main   <<<(NCELLS + MB - 1) / MB, 256, SM_TOT>>>(X, S, out + 2, bl, br);  // 4 <- profiled
    k_edgeA  <<<(E + 255) / 256, 256>>>(ei, att, E);              // 5
    k_edgeB  <<<1024, 256>>>(out + 2, E);                         // 6
    k_final  <<<1, 1>>>(out);                                     // 7
}